// round 17
// baseline (speedup 1.0000x reference)
#include <cuda_runtime.h>
#include <cuda_bf16.h>
#include <cuda_fp16.h>

#define N_ 32
#define T_ 48
#define NSM 148

// ---------------- scratch ----------------
__device__ float g_xt[(size_t)T_*N_*32*32];
__device__ float g_z1c[(size_t)T_*N_*16*28*28];               // conv1 pre-acts [t][n][c][hw]
__device__ __align__(256) __half g_h1h[(size_t)T_*N_*784*16]; // conv1 spikes fp16 [t][n][hw][c16]
__device__ float g_z2c[(size_t)T_*N_*576*32];                 // conv2 pre-acts [t][n][sp576][c32]
__device__ __align__(256) __half g_p1h[(size_t)T_*N_*144*32]; // pool1 spikes fp16 [t][n][pp144][c32]
__device__ float g_z3c[(size_t)T_*N_*32*8*8];                 // conv3 pre-acts [t][n][c][64]
__device__ float g_wt1[512*128];
__device__ __half g_w2s[2*25*32*16];
__device__ __half g_w3s[2*25*32*32];

// ---------------- fused prep ----------------
#define PW0 (N_*32*32)
#define PW1 (128*512)
#define PW2 (25*32*16)
#define PW3 (25*32*32)
#define PWT (PW0+PW1+PW2+PW3)
__global__ void k_prep(const float* __restrict__ x,  const float* __restrict__ Wf1,
                       const float* __restrict__ Wc2, const float* __restrict__ Wc3) {
    int gid = blockIdx.x*256 + threadIdx.x;
    if (gid < PW0) {
        int n = gid >> 10, hw = gid & 1023;
        const float* xp = x + (size_t)gid * T_;
        #pragma unroll
        for (int t = 0; t < T_; t++)
            g_xt[((size_t)t*N_ + n)*1024 + hw] = xp[t];
    } else if (gid < PW0+PW1) {
        int i = gid - PW0;
        int o = i >> 9, k = i & 511;
        g_wt1[k*128 + o] = Wf1[i];
    } else if (gid < PW0+PW1+PW2) {
        int i = gid - (PW0+PW1);
        int c = i % 16, o = (i/16) % 32, j = i/512;
        int kh = j/5, kw = j%5;
        float w = Wc2[((o*16 + c)*5 + kh)*5 + kw];
        __half h = __float2half_rn(w);
        float r = w - __half2float(h);
        g_w2s[0*12800 + i] = h;
        g_w2s[1*12800 + i] = __float2half_rn(r);
    } else if (gid < PWT) {
        int i = gid - (PW0+PW1+PW2);
        int c = i % 32, o = (i/32) % 32, j = i/1024;
        int kh = j/5, kw = j%5;
        float w = Wc3[((o*32 + c)*5 + kh)*5 + kw];
        __half h = __float2half_rn(w);
        float r = w - __half2float(h);
        g_w3s[0*25600 + i] = h;
        g_w3s[1*25600 + i] = __float2half_rn(r);
    }
}

// ---------------- mma / ldmatrix / cp.async helpers ----------------
__device__ __forceinline__ void mma16816(float* c, const unsigned* a,
                                         unsigned b0, unsigned b1) {
    asm volatile(
        "mma.sync.aligned.m16n8k16.row.col.f32.f16.f16.f32 "
        "{%0,%1,%2,%3}, {%4,%5,%6,%7}, {%8,%9}, {%0,%1,%2,%3};"
        : "+f"(c[0]), "+f"(c[1]), "+f"(c[2]), "+f"(c[3])
        : "r"(a[0]), "r"(a[1]), "r"(a[2]), "r"(a[3]), "r"(b0), "r"(b1));
}
__device__ __forceinline__ void ldsm_x4(unsigned* d, unsigned a) {
    asm volatile("ldmatrix.sync.aligned.m8n8.x4.shared.b16 {%0,%1,%2,%3}, [%4];"
                 : "=r"(d[0]), "=r"(d[1]), "=r"(d[2]), "=r"(d[3]) : "r"(a));
}
__device__ __forceinline__ void ldsm_x2(unsigned& d0, unsigned& d1, unsigned a) {
    asm volatile("ldmatrix.sync.aligned.m8n8.x2.shared.b16 {%0,%1}, [%2];"
                 : "=r"(d0), "=r"(d1) : "r"(a));
}
__device__ __forceinline__ void cp16(unsigned dst, const void* src) {
    asm volatile("cp.async.ca.shared.global [%0], [%1], 16;" :: "r"(dst), "l"(src));
}
#define CP_COMMIT() asm volatile("cp.async.commit_group;" ::: "memory")
#define CP_WAIT1()  asm volatile("cp.async.wait_group 1;" ::: "memory")

// ---------------- conv2: persistent, 512 thr (unchanged from R16) ----------------
#define C2_PAD 24
#define C2_TB  2
#define C2_TILES ((T_/C2_TB)*N_)
#define C2_BUFB (C2_TB*784*C2_PAD*2)
__global__ void __launch_bounds__(512, 1)
k_conv2_mma(const __half* __restrict__ h1h,
            const float* __restrict__ bc2,
            float* __restrict__ z2c) {
    extern __shared__ char sm[];
    __half* sIn = reinterpret_cast<__half*>(sm);
    __half* sW  = reinterpret_cast<__half*>(sm + 2*C2_BUFB);

    int tid = threadIdx.x;
    {
        const unsigned* src = reinterpret_cast<const unsigned*>(g_w2s);
        unsigned* dst = reinterpret_cast<unsigned*>(sW);
        for (int i = tid; i < 2*25*32*16/2; i += 512) {
            int e = i*2; int row = e >> 4; int c = e & 15;
            dst[(row*C2_PAD + c) >> 1] = src[i];
        }
    }

    int w    = tid >> 5;
    int lane = tid & 31;
    int qid  = lane >> 2;
    int rid  = lane & 3;
    int mi   = lane >> 3;
    int rr   = lane & 7;
    int matB = mi & 1;
    int ttw  = w >> 3;
    int sg   = w & 7;

    unsigned sInA = (unsigned)__cvta_generic_to_shared(sIn);
    unsigned sWA  = (unsigned)__cvta_generic_to_shared(sW);

    unsigned aaddr[2][2];
    #pragma unroll
    for (int s = 0; s < 2; s++)
        #pragma unroll
        for (int mt = 0; mt < 2; mt++) {
            int row = mt*16 + (mi & 1)*8 + rr;
            aaddr[s][mt] = sWA + (((s*25)*32 + row)*C2_PAD + (mi >> 1)*8)*2;
        }
    unsigned baddr[9];
    #pragma unroll
    for (int nt = 0; nt < 9; nt++) {
        int sp = sg*72 + nt*8 + rr;
        int ho = sp / 24, wo = sp % 24;
        baddr[nt] = sInA + ((ho*28 + wo)*C2_PAD + matB*8)*2;
    }
    constexpr unsigned TTOFF = 784*C2_PAD*2;

    auto stage = [&](int tile, int buf) {
        int n  = tile & (N_-1);
        int t0 = (tile >> 5) * C2_TB;
        for (int i = tid; i < C2_TB*784*2; i += 512) {
            int half16 = i & 1;
            int r = i >> 1;
            int hw = r % 784, tt = r / 784;
            const __half* src = h1h + (((size_t)(t0+tt)*N_ + n)*784 + hw)*16 + half16*8;
            unsigned dst = sInA + (unsigned)(buf*C2_BUFB)
                         + (unsigned)(((tt*784 + hw)*C2_PAD + half16*8)*2);
            cp16(dst, src);
        }
    };

    if (blockIdx.x < C2_TILES) stage(blockIdx.x, 0);
    CP_COMMIT();

    int it = 0;
    #pragma unroll 1
    for (int tile = blockIdx.x; tile < C2_TILES; tile += gridDim.x, it++) {
        int cur = it & 1;
        __syncthreads();
        int nxt = tile + gridDim.x;
        if (nxt < C2_TILES) stage(nxt, cur ^ 1);
        CP_COMMIT();
        CP_WAIT1();
        __syncthreads();

        unsigned bufoff = (unsigned)(cur*C2_BUFB) + (unsigned)(ttw*TTOFF);
        int n  = tile & (N_-1);
        int t0 = (tile >> 5) * C2_TB;

        float acc[2][9][4];
        #pragma unroll
        for (int mt = 0; mt < 2; mt++)
            #pragma unroll
            for (int nt = 0; nt < 9; nt++)
                #pragma unroll
                for (int r = 0; r < 4; r++) acc[mt][nt][r] = 0.f;

        #pragma unroll 1
        for (int j = 0; j < 25; j++) {
            int kh = j / 5, kw = j % 5;
            unsigned aoff = (unsigned)(j*32*C2_PAD*2);
            unsigned boff = bufoff + (unsigned)((kh*28 + kw)*C2_PAD*2);

            unsigned aF[2][2][4];
            #pragma unroll
            for (int s = 0; s < 2; s++)
                #pragma unroll
                for (int mt = 0; mt < 2; mt++)
                    ldsm_x4(aF[s][mt], aaddr[s][mt] + aoff);

            #pragma unroll
            for (int ng = 0; ng < 3; ng++) {
                unsigned bF[3][2];
                #pragma unroll
                for (int q = 0; q < 3; q++)
                    ldsm_x2(bF[q][0], bF[q][1], baddr[ng*3 + q] + boff);
                #pragma unroll
                for (int s = 0; s < 2; s++)
                    #pragma unroll
                    for (int q = 0; q < 3; q++)
                        #pragma unroll
                        for (int mt = 0; mt < 2; mt++)
                            mma16816(acc[mt][ng*3 + q], aF[s][mt], bF[q][0], bF[q][1]);
            }
        }

        {
            float* zb = z2c + ((size_t)(t0+ttw)*N_ + n)*576*32;
            #pragma unroll
            for (int mt = 0; mt < 2; mt++) {
                int o0 = mt*16 + qid;
                float b0 = bc2[o0], b1 = bc2[o0 + 8];
                #pragma unroll
                for (int nt = 0; nt < 9; nt++) {
                    int sp = sg*72 + nt*8 + rid*2;
                    zb[(size_t)sp*32 + o0]          = acc[mt][nt][0] + b0;
                    zb[(size_t)(sp+1)*32 + o0]      = acc[mt][nt][1] + b0;
                    zb[(size_t)sp*32 + o0 + 8]      = acc[mt][nt][2] + b1;
                    zb[(size_t)(sp+1)*32 + o0 + 8]  = acc[mt][nt][3] + b1;
                }
            }
        }
    }
}

// ---------------- conv3: persistent, 512 thr, A-fragment double buffer ----------------
#define C3_PAD 40
#define C3_TB  4
#define C3_TILES ((T_/C3_TB)*N_)
#define C3_BUFB (C3_TB*144*C3_PAD*2)
__global__ void __launch_bounds__(512, 1)
k_conv3_mma(const __half* __restrict__ p1h,
            const float* __restrict__ bc3,
            float* __restrict__ z3c) {
    extern __shared__ char sm[];
    __half* sW  = reinterpret_cast<__half*>(sm);
    __half* sIn = reinterpret_cast<__half*>(sm + 2*25*32*C3_PAD*2);

    int tid = threadIdx.x;
    {
        const unsigned* src = reinterpret_cast<const unsigned*>(g_w3s);
        unsigned* dst = reinterpret_cast<unsigned*>(sW);
        for (int i = tid; i < 2*25*32*32/2; i += 512) {
            int e = i*2; int row = e >> 5; int c = e & 31;
            dst[(row*C3_PAD + c) >> 1] = src[i];
        }
    }

    int w    = tid >> 5;
    int lane = tid & 31;
    int qid  = lane >> 2;
    int rid  = lane & 3;
    int mi   = lane >> 3;
    int rr   = lane & 7;
    int matB = mi & 1;
    int tp   = w >> 3;
    int mt   = (w >> 2) & 1;
    int ntp  = w & 3;

    unsigned sInA = (unsigned)__cvta_generic_to_shared(sIn);
    unsigned sWA  = (unsigned)__cvta_generic_to_shared(sW);

    unsigned aaddr[2];
    #pragma unroll
    for (int s = 0; s < 2; s++) {
        int row = mt*16 + (mi & 1)*8 + rr;
        aaddr[s] = sWA + (((s*25)*32 + row)*C3_PAD + (mi >> 1)*8)*2;
    }
    unsigned baddr[2];
    #pragma unroll
    for (int q = 0; q < 2; q++) {
        int ntr = ntp*2 + q;
        baddr[q] = sInA + ((ntr*12 + rr)*C3_PAD + matB*8)*2;
    }
    constexpr unsigned TTOFF3 = 144*C3_PAD*2;

    auto stage = [&](int tile, int buf) {
        int n  = tile & (N_-1);
        int t0 = (tile >> 5) * C3_TB;
        for (int i = tid; i < C3_TB*144*4; i += 512) {
            int q  = i & 3;
            int r  = i >> 2;
            int hw = r % 144, tt = r / 144;
            const __half* src = p1h + (((size_t)(t0+tt)*N_ + n)*144 + hw)*32 + q*8;
            unsigned dst = sInA + (unsigned)(buf*C3_BUFB)
                         + (unsigned)(((tt*144 + hw)*C3_PAD + q*8)*2);
            cp16(dst, src);
        }
    };

    auto loadA = [&](int j, unsigned (&aF)[2][2][4]) {
        #pragma unroll
        for (int s = 0; s < 2; s++)
            #pragma unroll
            for (int kc = 0; kc < 2; kc++)
                ldsm_x4(aF[s][kc], aaddr[s] + (unsigned)((j*32*C3_PAD + kc*16)*2));
    };

    if (blockIdx.x < C3_TILES) stage(blockIdx.x, 0);
    CP_COMMIT();

    int o0 = mt*16 + qid;
    float bb0 = bc3[o0], bb1 = bc3[o0 + 8];

    int it = 0;
    #pragma unroll 1
    for (int tile = blockIdx.x; tile < C3_TILES; tile += gridDim.x, it++) {
        int cur = it & 1;
        __syncthreads();
        int nxt = tile + gridDim.x;
        if (nxt < C3_TILES) stage(nxt, cur ^ 1);
        CP_COMMIT();
        CP_WAIT1();
        __syncthreads();

        unsigned bufoff = (unsigned)(cur*C3_BUFB);
        int n  = tile & (N_-1);
        int t0 = (tile >> 5) * C3_TB;

        float acc[2][2][4];
        #pragma unroll
        for (int u = 0; u < 2; u++)
            #pragma unroll
            for (int q = 0; q < 2; q++)
                #pragma unroll
                for (int r = 0; r < 4; r++) acc[u][q][r] = 0.f;

        unsigned toffA = bufoff + (tp*2)*TTOFF3;
        unsigned toffB = bufoff + (tp*2+1)*TTOFF3;

        unsigned aFb[2][2][2][4];   // double-buffered A fragments
        loadA(0, aFb[0]);

        #pragma unroll 1
        for (int j = 0; j < 25; j++) {
            int ab = j & 1;
            if (j < 24) loadA(j + 1, aFb[ab ^ 1]);

            int kh = j / 5, kw = j % 5;
            unsigned bF[2][2][2][2];
            #pragma unroll
            for (int kc = 0; kc < 2; kc++) {
                unsigned bo = (unsigned)(((kh*12 + kw)*C3_PAD + kc*16)*2);
                #pragma unroll
                for (int q = 0; q < 2; q++) {
                    ldsm_x2(bF[0][kc][q][0], bF[0][kc][q][1], baddr[q] + bo + toffA);
                    ldsm_x2(bF[1][kc][q][0], bF[1][kc][q][1], baddr[q] + bo + toffB);
                }
            }
            #pragma unroll
            for (int s = 0; s < 2; s++)
                #pragma unroll
                for (int kc = 0; kc < 2; kc++)
                    #pragma unroll
                    for (int u = 0; u < 2; u++)
                        #pragma unroll
                        for (int q = 0; q < 2; q++)
                            mma16816(acc[u][q], aFb[ab][s][kc], bF[u][kc][q][0], bF[u][kc][q][1]);
        }

        #pragma unroll
        for (int u = 0; u < 2; u++) {
            float* zb = z3c + ((size_t)(t0 + tp*2 + u)*N_ + n)*32*64;
            #pragma unroll
            for (int q = 0; q < 2; q++) {
                int sp = (ntp*2 + q)*8 + rid*2;
                float2 d0; d0.x = acc[u][q][0] + bb0; d0.y = acc[u][q][1] + bb0;
                float2 d1; d1.x = acc[u][q][2] + bb1; d1.y = acc[u][q][3] + bb1;
                *reinterpret_cast<float2*>(zb + (size_t)o0*64 + sp)     = d0;
                *reinterpret_cast<float2*>(zb + (size_t)(o0+8)*64 + sp) = d1;
            }
        }
    }
}

// ---------------- conv1 scalar (unchanged) ----------------
template<int CIN,int COUT,int HIN,int WIN,int GO,int WOT,int HOT,int TV,int MINB>
__global__ void
__launch_bounds__(((WIN-4)/WOT)*(COUT/GO)*HOT, MINB)
k_conv(const float* __restrict__ in,
       const float* __restrict__ Wc,
       const float* __restrict__ bc,
       float* __restrict__ z) {
    constexpr int HOUT = HIN-4, WOUT = WIN-4;
    constexpr int NWG  = WOUT/WOT;
    constexpr int NOG  = COUT/GO;
    constexpr int LANES = NWG*NOG;
    constexpr int HBLK = HOUT/HOT;
    constexpr int M    = CIN*5;
    constexpr size_t TS_IN  = (size_t)N_*CIN*HIN*WIN;
    constexpr size_t TS_OUT = (size_t)N_*COUT*HOUT*WOUT;
    extern __shared__ float ws[];
    {
        int tid = threadIdx.y*LANES + threadIdx.x;
        for (int i = tid; i < COUT*CIN*25; i += LANES*HOT) {
            int oc = i % COUT;
            int ck = i / COUT;
            ws[i] = Wc[oc*CIN*25 + ck];
        }
    }
    __syncthreads();

    int hb = blockIdx.x % HBLK;
    int t0 = (blockIdx.x / HBLK) * TV;
    int n  = blockIdx.y;
    int wg = threadIdx.x % NWG;
    int og = threadIdx.x / NWG;
    int wo = wg * WOT;
    int ho = hb*HOT + threadIdx.y;

    float acc[GO][WOT][TV];
    #pragma unroll
    for (int g = 0; g < GO; g++) {
        float b = bc[og*GO + g];
        #pragma unroll
        for (int ww = 0; ww < WOT; ww++)
            #pragma unroll
            for (int tv = 0; tv < TV; tv++) acc[g][ww][tv] = b;
    }

    const float* inb = in + (size_t)t0*TS_IN + (size_t)n*CIN*HIN*WIN
                          + (size_t)ho*WIN + wo;

    float va[WOT+4][TV], vb[WOT+4][TV];

    auto load_v = [&](int m, float (&v)[WOT+4][TV]) {
        int c = m / 5, kh = m % 5;
        const float* ip = inb + ((size_t)c*HIN + kh)*WIN;
        #pragma unroll
        for (int tv = 0; tv < TV; tv++) {
            const float2* p2 = reinterpret_cast<const float2*>(ip + (size_t)tv*TS_IN);
            #pragma unroll
            for (int j2 = 0; j2 < (WOT+4)/2; j2++) {
                float2 d = p2[j2];
                v[2*j2][tv]   = d.x;
                v[2*j2+1][tv] = d.y;
            }
        }
    };

    auto fma_step = [&](int m, float (&v)[WOT+4][TV]) {
        #pragma unroll
        for (int kw = 0; kw < 5; kw++) {
            float wreg[GO];
            if constexpr (GO == 4) {
                float4 w4 = *reinterpret_cast<const float4*>(&ws[(m*5 + kw)*COUT + og*4]);
                wreg[0] = w4.x; wreg[1] = w4.y; wreg[2] = w4.z; wreg[3] = w4.w;
            } else if constexpr (GO == 2) {
                float2 w2 = *reinterpret_cast<const float2*>(&ws[(m*5 + kw)*COUT + og*2]);
                wreg[0] = w2.x; wreg[1] = w2.y;
            } else {
                #pragma unroll
                for (int g = 0; g < GO; g++) wreg[g] = ws[(m*5 + kw)*COUT + og*GO + g];
            }
            #pragma unroll
            for (int g = 0; g < GO; g++)
                #pragma unroll
                for (int ww = 0; ww < WOT; ww++)
                    #pragma unroll
                    for (int tv = 0; tv < TV; tv++)
                        acc[g][ww][tv] += v[ww+kw][tv] * wreg[g];
        }
    };

    load_v(0, va);
    int m = 0;
    #pragma unroll 1
    for (; m + 2 <= M; m += 2) {
        load_v(m + 1, vb);
        fma_step(m, va);
        if (m + 2 < M) load_v(m + 2, va);
        fma_step(m + 1, vb);
    }
    if (m < M) fma_step(m, va);

    float* zb = z + (size_t)t0*TS_OUT + (size_t)n*COUT*HOUT*WOUT
                  + (size_t)og*GO*HOUT*WOUT + (size_t)ho*WOUT + wo;
    #pragma unroll
    for (int tv = 0; tv < TV; tv++)
        #pragma unroll
        for (int g = 0; g < GO; g++) {
            float* op = zb + (size_t)tv*TS_OUT + (size_t)g*HOUT*WOUT;
            #pragma unroll
            for (int j2 = 0; j2 < WOT/2; j2++) {
                float2 d; d.x = acc[g][2*j2][tv]; d.y = acc[g][2*j2+1][tv];
                reinterpret_cast<float2*>(op)[j2] = d;
            }
        }
}

// ---------------- layer-1 LIF scan ----------------
__global__ void k_scan1t(const float* __restrict__ z, __half* __restrict__ hout) {
    int idx = blockIdx.x * blockDim.x + threadIdx.x;
    if (idx >= N_*784) return;
    int n = idx / 784, hw = idx % 784;
    float u[16];
    #pragma unroll
    for (int c = 0; c < 16; c++) u[c] = 0.f;
    #pragma unroll 2
    for (int t = 0; t < T_; t++) {
        const float* zp = z + ((size_t)t*N_ + n)*16*784 + hw;
        __half hh[16];
        #pragma unroll
        for (int c = 0; c < 16; c++) {
            u[c] += zp[(size_t)c*784];
            float s = (u[c] >= 1.0f) ? 1.0f : 0.0f;
            u[c] -= s;
            hh[c] = __float2half_rn(s);
        }
        uint4* op = reinterpret_cast<uint4*>(hout + (((size_t)t*N_ + n)*784 + hw)*16);
        op[0] = reinterpret_cast<uint4*>(hh)[0];
        op[1] = reinterpret_cast<uint4*>(hh)[1];
    }
}

// ---------------- scanpool24 channel-last ----------------
__global__ void k_scanpool2c(const float* __restrict__ z, __half* __restrict__ hout) {
    int idx = blockIdx.x * blockDim.x + threadIdx.x;
    if (idx >= N_*144*32) return;
    int c  = idx & 31;
    int pp = (idx >> 5) % 144;
    int n  = idx / (144*32);
    int ho = pp / 12, wo = pp % 12;
    int s00 = (2*ho)*24 + 2*wo;
    const float* zb = z + c + (size_t)s00*32;
    float u0 = 0.f, u1 = 0.f, u2 = 0.f, u3 = 0.f, up = 0.f;
    #pragma unroll 4
    for (int t = 0; t < T_; t++) {
        const float* p = zb + ((size_t)t*N_ + n)*576*32;
        u0 += p[0];      float sp0 = (u0 >= 1.0f) ? 1.0f : 0.0f; u0 -= sp0;
        u1 += p[32];     float sp1 = (u1 >= 1.0f) ? 1.0f : 0.0f; u1 -= sp1;
        u2 += p[24*32];  float sp2 = (u2 >= 1.0f) ? 1.0f : 0.0f; u2 -= sp2;
        u3 += p[25*32];  float sp3 = (u3 >= 1.0f) ? 1.0f : 0.0f; u3 -= sp3;
        up += 0.25f*(sp0 + sp1 + sp2 + sp3);
        float so = (up >= 1.0f) ? 1.0f : 0.0f; up -= so;
        hout[(((size_t)t*N_ + n)*144 + pp)*32 + c] = __float2half_rn(so);
    }
}

// ---------------- fused tail: scanpool8 + fc1 + fc1-scan + fc2 + fc2-scan + mean ----------------
// One block per n; dynamic smem: sp2[48][512] floats + z1s[48][128] floats.
__global__ void __launch_bounds__(512, 1)
k_tail(const float* __restrict__ z3c,
       const float* __restrict__ bf1,
       const float* __restrict__ Wf2, const float* __restrict__ bf2,
       float* __restrict__ out) {
    extern __shared__ float smf[];
    float* sp2 = smf;                 // [48][512]
    float* z1s = smf + 48*512;        // [48][128]

    int n = blockIdx.x, tid = threadIdx.x;

    // phase 1: scanpool8 -> sp2[t][k], k = c*16 + po  (matches Wf1 ochw flattening)
    {
        int c  = tid >> 4;
        int po = tid & 15;
        int ho = po >> 2, wo = po & 3;
        const float* ip = z3c + ((size_t)n*32 + c)*64 + (size_t)(2*ho)*8 + 2*wo;
        float u0 = 0.f, u1 = 0.f, u2 = 0.f, u3 = 0.f, up = 0.f;
        #pragma unroll 4
        for (int t = 0; t < T_; t++) {
            const float* p = ip + (size_t)t*N_*32*64;
            u0 += p[0]; float s0 = (u0 >= 1.0f) ? 1.0f : 0.0f; u0 -= s0;
            u1 += p[1]; float s1 = (u1 >= 1.0f) ? 1.0f : 0.0f; u1 -= s1;
            u2 += p[8]; float s2 = (u2 >= 1.0f) ? 1.0f : 0.0f; u2 -= s2;
            u3 += p[9]; float s3 = (u3 >= 1.0f) ? 1.0f : 0.0f; u3 -= s3;
            up += 0.25f*(s0 + s1 + s2 + s3);
            float sp = (up >= 1.0f) ? 1.0f : 0.0f; up -= sp;
            sp2[t*512 + tid] = sp;
        }
    }
    __syncthreads();

    // phase 2: fc1 for all t -> z1s[t][o]
    {
        int tq = tid >> 7;        // 0..3
        int o  = tid & 127;
        float b = bf1[o];
        #pragma unroll 1
        for (int tb = tq; tb < T_; tb += 4) {
            float acc = b;
            const float* sp = sp2 + tb*512;
            #pragma unroll 8
            for (int k = 0; k < 512; k++)
                acc += sp[k] * g_wt1[k*128 + o];
            z1s[tb*128 + o] = acc;
        }
    }
    __syncthreads();

    // phase 3: head (threads 0..127)
    if (tid < 128) {
        int wid = tid >> 5, lane = tid & 31;
        __shared__ float s1[128];
        float wr[4] = {0.f, 0.f, 0.f, 0.f};
        float b2 = 0.f;
        if (wid < 2) {
            #pragma unroll
            for (int k = 0; k < 4; k++) wr[k] = Wf2[wid*128 + lane + 32*k];
            b2 = bf2[wid];
        }
        float u1 = 0.f, u2 = 0.f, ssum = 0.f;
        for (int t = 0; t < T_; t++) {
            float z = z1s[t*128 + tid];
            u1 += z;
            float s = (u1 >= 1.0f) ? 1.0f : 0.0f;
            u1 -= s;
            s1[tid] = s;
            __syncwarp();
            asm volatile("bar.sync 1, 128;" ::: "memory");
            if (wid < 2) {
                float d = s1[lane]*wr[0] + s1[lane+32]*wr[1]
                        + s1[lane+64]*wr[2] + s1[lane+96]*wr[3];
                #pragma unroll
                for (int off = 16; off > 0; off >>= 1)
                    d += __shfl_xor_sync(0xFFFFFFFFu, d, off);
                u2 += d + b2;
                float s2 = (u2 >= 1.0f) ? 1.0f : 0.0f;
                u2 -= s2;
                ssum += s2;
            }
            asm volatile("bar.sync 1, 128;" ::: "memory");
        }
        if (wid < 2 && lane == 0) out[n*2 + wid] = ssum * (1.0f / T_);
    }
}

// ---------------- launch ----------------
extern "C" void kernel_launch(void* const* d_in, const int* in_sizes, int n_in,
                              void* d_out, int out_size) {
    (void)in_sizes; (void)n_in; (void)out_size;
    const float* x   = (const float*)d_in[0];
    const float* Wc1 = (const float*)d_in[1];
    const float* bc1 = (const float*)d_in[2];
    const float* Wc2 = (const float*)d_in[3];
    const float* bc2 = (const float*)d_in[4];
    const float* Wc3 = (const float*)d_in[5];
    const float* bc3 = (const float*)d_in[6];
    const float* Wf1 = (const float*)d_in[7];
    const float* bf1 = (const float*)d_in[8];
    const float* Wf2 = (const float*)d_in[9];
    const float* bf2 = (const float*)d_in[10];
    float* out = (float*)d_out;

    float *p_xt, *p_z1c, *p_z2c, *p_z3c;
    __half *p_h1h, *p_p1h;
    cudaGetSymbolAddress((void**)&p_xt,  g_xt);
    cudaGetSymbolAddress((void**)&p_z1c, g_z1c);
    cudaGetSymbolAddress((void**)&p_h1h, g_h1h);
    cudaGetSymbolAddress((void**)&p_z2c, g_z2c);
    cudaGetSymbolAddress((void**)&p_p1h, g_p1h);
    cudaGetSymbolAddress((void**)&p_z3c, g_z3c);

    auto c1 = k_conv<1,16,32,32,4,4,7,2,2>;

    constexpr int SMEM_C2 = 2*C2_BUFB + 2*25*32*C2_PAD*2;
    constexpr int SMEM_C3 = 2*25*32*C3_PAD*2 + 2*C3_BUFB;
    constexpr int SMEM_TAIL = (48*512 + 48*128)*4;   // 98304 + 24576 = 122880
    cudaFuncSetAttribute(k_conv2_mma, cudaFuncAttributeMaxDynamicSharedMemorySize, SMEM_C2);
    cudaFuncSetAttribute(k_conv3_mma, cudaFuncAttributeMaxDynamicSharedMemorySize, SMEM_C3);
    cudaFuncSetAttribute(k_tail, cudaFuncAttributeMaxDynamicSharedMemorySize, SMEM_TAIL);

    // launch order: k_conv2_mma stays launch #4 (ncu capture slot)
    k_prep<<<(PWT + 255)/256, 256>>>(x, Wf1, Wc2, Wc3);                        // 1
    c1<<<dim3(4*(T_/2), N_), dim3(28, 7), 16*1*25*4>>>(p_xt, Wc1, bc1, p_z1c); // 2
    k_scan1t<<<(N_*784 + 255)/256, 256>>>(p_z1c, p_h1h);                       // 3
    k_conv2_mma<<<NSM, 512, SMEM_C2>>>(p_h1h, bc2, p_z2c);                     // 4 <- profiled
    k_scanpool2c<<<(N_*144*32 + 255)/256, 256>>>(p_z2c, p_p1h);                // 5
    k_conv3_mma<<<NSM, 512, SMEM_C3>>>(p_p1h, bc3, p_z3c);                     // 6
    k_tail<<<N_, 512, SMEM_TAIL>>>(p_z3c, bf1, Wf2, bf2, out);                 // 7
}